// round 14
// baseline (speedup 1.0000x reference)
#include <cuda_runtime.h>
#include <cstdint>

// Problem constants (fixed shapes from reference)
#define T_IMG 15
#define C1    6
#define HW    224
#define O1    30
#define O2    240
#define PH    112                      // pooled / layer-2 spatial size
#define N2    (T_IMG*O2*PH*PH)         // 45,158,400 elements per output tensor
#define ZCAP  (T_IMG*O1*PH*PH)
#define NSCR  (T_IMG*PH)               // 1680 screen blocks
#define NFILL (N2/8/256)               // 22050 fill blocks (2 float4 / thread)
#define GRID_FUSED (NSCR*14 + (NFILL - NSCR*13))   // 23730

// Scratch (device globals — no allocation allowed)
__device__ float d_S[O2*9];            // per-o border-class full sums of w2
__device__ int   d_zero_count;
__device__ int   d_zero_list[ZCAP];

// ---------------------------------------------------------------------------
// prep: reset counter; build S[o][rc][cc] = sum over border-allowed (kh,kw)
// and all c of w2 (zero padding kills kernel rows/cols at edges).
// rc/cc: 0 -> coord==0 (k in {1,2}); 1 -> interior; 2 -> coord==PH-1 (k in {0,1})
// ---------------------------------------------------------------------------
__global__ void prep_kernel(const float* __restrict__ w2) {
    int o = blockIdx.x;
    int j = threadIdx.x;
    if (o == 0 && j == 9) d_zero_count = 0;
    if (j < 9) {
        int rc = j / 3, cc = j % 3;
        int kh_lo = (rc == 0) ? 1 : 0;
        int kh_hi = (rc == 2) ? 1 : 2;
        int kw_lo = (cc == 0) ? 1 : 0;
        int kw_hi = (cc == 2) ? 1 : 2;
        float s = 0.f;
        for (int kh = kh_lo; kh <= kh_hi; ++kh)
            for (int kw = kw_lo; kw <= kw_hi; ++kw)
                for (int c = 0; c < O1; ++c)
                    s += w2[((o*O1 + c)*3 + kh)*3 + kw];
        d_S[o*9 + j] = s;
    }
}

// ---------------------------------------------------------------------------
// fused kernel, interleaved block roles (1 screen block per 14-block group so
// the latency-bound screening hides under the DRAM-bound fill stream):
//
// SCREEN role (one (t, pooled row py) each): compute B = zero-padded 5x5x6
//   box-sum of the input at the representative conv pixel (2py,2px). Since
//   input >= 0, pot_o(rep) >= wmin_o * B; if that exceeds 15 the pooled pixel
//   provably fires (pool-max >= rep). Otherwise resolve EXACTLY inline: full
//   2x2 conv-pixel max from gmem; true zero spikes -> d_zero_list. Negative
//   wmin_o => product <= 0 => always resolved exactly => sound for any weights.
//
// FILL role: pot2 assuming all pooled spikes fire = S[o][rc(y)][cc(x)],
//   thresholded at 10; writes BOTH pot and spk final. Two consecutive-strided
//   float4 stores per thread (512 float4 per block) with evict-first hint.
// ---------------------------------------------------------------------------
__global__ void __launch_bounds__(256) fused_kernel(
    const float* __restrict__ in, const float* __restrict__ w1,
    float* __restrict__ spk, float* __restrict__ pot)
{
    const int bid = blockIdx.x;
    const int tid = threadIdx.x;
    const int g = bid / 14, l = bid - g * 14;

    if (l == 13 && g < NSCR) {
        // ------------------------- SCREEN role -------------------------
        __shared__ float sV[228];
        __shared__ float swmin[O1];
        __shared__ float swminmin;

        const int t  = g / PH;
        const int py = g % PH;

        // per-filter min of w1 (30 filters x 150 weights), L1-hot
        if (tid < O1) {
            const float* w = w1 + tid * (C1*25);
            float m = w[0];
            for (int k = 1; k < C1*25; ++k) m = fminf(m, w[k]);
            swmin[tid] = m;
        }
        __syncthreads();
        if (tid == 0) {
            float m = swmin[0];
            #pragma unroll
            for (int o = 1; o < O1; ++o) m = fminf(m, swmin[o]);
            swminmin = m;
        }

        // column sums over the 5 conv rows x 6 channels (zero padding)
        const float* base = in + (size_t)t * C1*HW*HW;
        if (tid < 228) {
            int x = tid - 2;
            float s = 0.f;
            if ((unsigned)x < HW) {
                int y0 = 2*py - 2;
                #pragma unroll
                for (int r = 0; r < 5; ++r) {
                    int y = y0 + r;
                    if ((unsigned)y < HW) {
                        #pragma unroll
                        for (int c = 0; c < C1; ++c)
                            s += base[(c*HW + y)*HW + x];
                    }
                }
            }
            sV[tid] = s;
        }
        __syncthreads();

        if (tid >= PH) return;
        const int px = tid;
        float B = sV[2*px] + sV[2*px+1] + sV[2*px+2] + sV[2*px+3] + sV[2*px+4];
        if (swminmin * B > 15.0f) return;     // every filter provably fires

        for (int o = 0; o < O1; ++o) {
            if (swmin[o] * B > 15.0f) continue;
            // exact inline resolution: full 2x2 conv-pixel max
            float m = -1e30f;
            for (int yy = 0; yy < 2; ++yy) {
                for (int xx = 0; xx < 2; ++xx) {
                    float p = 0.f;
                    for (int c = 0; c < C1; ++c)
                        for (int kh = 0; kh < 5; ++kh) {
                            int iy = 2*py + yy - 2 + kh;
                            if ((unsigned)iy >= HW) continue;
                            for (int kw = 0; kw < 5; ++kw) {
                                int ix = 2*px + xx - 2 + kw;
                                if ((unsigned)ix >= HW) continue;
                                p += base[((size_t)c*HW + iy)*HW + ix]
                                   * w1[((o*C1 + c)*5 + kh)*5 + kw];
                            }
                        }
                    m = fmaxf(m, p);
                }
            }
            if (!(m > 15.0f)) {
                int s = atomicAdd(&d_zero_count, 1);
                d_zero_list[s] = ((t*O1 + o)*PH + py)*PH + px;
            }
        }
    } else {
        // -------------------------- FILL role --------------------------
        int fidx = (g < NSCR) ? (g*13 + l) : (NSCR*13 + bid - NSCR*14);
        #pragma unroll
        for (int h = 0; h < 2; ++h) {
            int i = fidx * 512 + h * 256 + tid;
            int row = i / 28;            // (t*240 + o)*112 + y
            int xq  = i % 28;
            int y = row % PH;
            int o = (row / PH) % O2;
            int rc = (y == 0) ? 0 : ((y == PH-1) ? 2 : 1);
            const float* Sp = &d_S[o*9 + rc*3];
            float v0 = Sp[0], v1 = Sp[1], v2 = Sp[2];
            float4 p;
            p.x = (xq == 0)  ? v0 : v1;
            p.y = v1; p.z = v1;
            p.w = (xq == 27) ? v2 : v1;
            float4 s;
            s.x = (p.x > 10.0f) ? 1.0f : 0.0f; if (!(p.x > 10.0f)) p.x = 0.0f;
            s.y = (p.y > 10.0f) ? 1.0f : 0.0f; if (!(p.y > 10.0f)) p.y = 0.0f;
            s.z = (p.z > 10.0f) ? 1.0f : 0.0f; if (!(p.z > 10.0f)) p.z = 0.0f;
            s.w = (p.w > 10.0f) ? 1.0f : 0.0f; if (!(p.w > 10.0f)) p.w = 0.0f;
            __stcs(((float4*)spk) + i, s);
            __stcs(((float4*)pot) + i, p);
        }
    }
}

// ---------------------------------------------------------------------------
// epilogue (merged correct+fixup, gather form, idempotent — no atomics, one
// launch): for each (zero-spike e, channel o, 3x3 offset), compute the FULL
// exact final value of the affected pixel:
//     v = S[o][rc(y)][cc(x)] - sum over ALL zero spikes z touching (y,x) of
//         w2[o, c_z, y-py_z+1, x-px_z+1]
// then threshold at 10 and write pot & spk. Pixels covered by multiple
// entries get identical writes -> race-free. Empty list -> immediate exit.
// ---------------------------------------------------------------------------
__global__ void epilogue_kernel(const float* __restrict__ w2,
                                float* __restrict__ spk, float* __restrict__ pot) {
    int n = d_zero_count;
    if (n == 0) return;
    int total  = n * O2 * 9;
    int stride = gridDim.x * blockDim.x;
    for (int i = blockIdx.x*blockDim.x + threadIdx.x; i < total; i += stride) {
        int e   = i / (O2*9);
        int rem = i % (O2*9);
        int o   = rem / 9;
        int k   = rem % 9;
        int packed = d_zero_list[e];
        int px = packed % PH;
        int py = (packed / PH) % PH;
        int t  =  packed / (PH*PH*O1);
        int y = py + 1 - (k / 3);
        int x = px + 1 - (k % 3);
        if ((unsigned)y >= PH || (unsigned)x >= PH) continue;
        int rc = (y == 0) ? 0 : ((y == PH-1) ? 2 : 1);
        int cc = (x == 0) ? 0 : ((x == PH-1) ? 2 : 1);
        float v = d_S[o*9 + rc*3 + cc];
        for (int z = 0; z < n; ++z) {
            int pz = d_zero_list[z];
            int tz = pz / (PH*PH*O1);
            if (tz != t) continue;
            int pxz = pz % PH;
            int pyz = (pz / PH) % PH;
            int dy = y - pyz + 1, dx = x - pxz + 1;
            if ((unsigned)dy >= 3 || (unsigned)dx >= 3) continue;
            int cz = (pz / (PH*PH)) % O1;
            v -= w2[(o*O1 + cz)*9 + dy*3 + dx];
        }
        bool fire = v > 10.0f;
        size_t idx = (((size_t)t*O2 + o)*PH + y)*PH + x;
        pot[idx] = fire ? v : 0.0f;
        spk[idx] = fire ? 1.0f : 0.0f;
    }
}

// ---------------------------------------------------------------------------
extern "C" void kernel_launch(void* const* d_in, const int* in_sizes, int n_in,
                              void* d_out, int out_size) {
    const float* input = (const float*)d_in[0];
    const float* w1    = (const float*)d_in[1];
    const float* w2    = (const float*)d_in[2];
    float* spk = (float*)d_out;
    float* pot = spk + (size_t)(out_size / 2);

    prep_kernel<<<O2, 32>>>(w2);
    fused_kernel<<<GRID_FUSED, 256>>>(input, w1, spk, pot);
    epilogue_kernel<<<192, 256>>>(w2, spk, pot);
    (void)in_sizes; (void)n_in;
}